// round 1
// baseline (speedup 1.0000x reference)
#include <cuda_runtime.h>

#define IW 1920
#define IH 1080
#define IB 8
#define NPIX (IW * IH)
#define NTOT (IB * NPIX)

// Scratch (no cudaMalloc allowed)
__device__ float         g_smooth[NTOT];
__device__ unsigned char g_dir[NTOT];
__device__ unsigned char g_edge[2][NTOT];
__device__ unsigned char g_low[2][NTOT];

// ---------------------------------------------------------------------------
// Kernel 1: 5x5 gaussian on x/255 (zero-padded per plane)
// ---------------------------------------------------------------------------
__global__ void k_gauss(const float* __restrict__ x, const float* __restrict__ gw) {
    __shared__ float sh[12][36];
    __shared__ float wg[25];
    const int b  = blockIdx.z;
    const int bx = blockIdx.x * 32, by = blockIdx.y * 8;
    const int tx = threadIdx.x, ty = threadIdx.y;
    const int tid = ty * 32 + tx;
    if (tid < 25) wg[tid] = gw[tid];
    const float* img = x + b * NPIX;
    for (int i = tid; i < 12 * 36; i += 256) {
        int r = i / 36, c = i % 36;
        int yy = by + r - 2, xx = bx + c - 2;
        float v = 0.f;
        if (yy >= 0 && yy < IH && xx >= 0 && xx < IW) v = img[yy * IW + xx];
        sh[r][c] = v;
    }
    __syncthreads();
    float s = 0.f;
#pragma unroll
    for (int i = 0; i < 5; i++)
#pragma unroll
        for (int j = 0; j < 5; j++)
            s = fmaf(wg[i * 5 + j], sh[ty + i][tx + j], s);
    g_smooth[b * NPIX + (by + ty) * IW + (bx + tx)] = s * (1.0f / 255.0f);
}

// ---------------------------------------------------------------------------
// Kernel 2: sobel -> mag*255 (to d_out), ang_out (to d_out), direction class
// ---------------------------------------------------------------------------
__global__ void k_sobel(const float* __restrict__ sxw, const float* __restrict__ syw,
                        float* __restrict__ magOut, float* __restrict__ angOut) {
    __shared__ float sh[10][34];
    __shared__ float wx[9], wy[9];
    const int b  = blockIdx.z;
    const int bx = blockIdx.x * 32, by = blockIdx.y * 8;
    const int tx = threadIdx.x, ty = threadIdx.y;
    const int tid = ty * 32 + tx;
    if (tid < 9) { wx[tid] = sxw[tid]; wy[tid] = syw[tid]; }
    const float* img = g_smooth + b * NPIX;
    for (int i = tid; i < 10 * 34; i += 256) {
        int r = i / 34, c = i % 34;
        int yy = by + r - 1, xx = bx + c - 1;
        float v = 0.f;
        if (yy >= 0 && yy < IH && xx >= 0 && xx < IW) v = img[yy * IW + xx];
        sh[r][c] = v;
    }
    __syncthreads();
    float gx = 0.f, gy = 0.f;
#pragma unroll
    for (int i = 0; i < 3; i++)
#pragma unroll
        for (int j = 0; j < 3; j++) {
            float v = sh[ty + i][tx + j];
            gx = fmaf(wx[i * 3 + j], v, gx);
            gy = fmaf(wy[i * 3 + j], v, gy);
        }
    const int idx = b * NPIX + (by + ty) * IW + (bx + tx);
    float mag = sqrtf(gx * gx + gy * gy + 1e-6f);
    magOut[idx] = mag * 255.0f;
    float ang = atan2f(gy, gx);
    float t = ang + 3.14159274101257324f;         // float32(pi)
    t = fmodf(t, 6.28318548202514648f);           // float32(2*pi)
    float deg = t * 57.2957801818847656f;         // float32(180/pi)
    angOut[idx] = fmodf(deg, 180.0f);
    int q = (int)rintf(deg / 45.0f);              // round-half-even, matches jnp.round
    g_dir[idx] = (unsigned char)(q & 3);          // ((q%8)*45)%180 / 45 == q%4
}

// ---------------------------------------------------------------------------
// Kernel 3: NMS (wrap-around neighbors per jnp.roll) + double threshold
// ---------------------------------------------------------------------------
__global__ void k_nms(const float* __restrict__ mag) {
    const int b = blockIdx.z;
    const int x = blockIdx.x * 32 + threadIdx.x;
    const int y = blockIdx.y * 8 + threadIdx.y;
    const float* p = mag + b * NPIX;
    const int idx = b * NPIX + y * IW + x;
    const float m0 = p[y * IW + x];
    const int xl = (x == 0) ? (IW - 1) : (x - 1);
    const int xr = (x == IW - 1) ? 0 : (x + 1);
    const int yu = (y == 0) ? (IH - 1) : (y - 1);
    const int yd = (y == IH - 1) ? 0 : (y + 1);
    const int cls = g_dir[idx];
    // cls0: (y,xr)/(y,xl)  cls1: (yd,xr)/(yu,x) [ref bug kept]
    // cls2: (yd,x)/(yu,x)  cls3: (yd,xl)/(yu,xr)
    int ay = (cls == 0) ? y : yd;
    int ax = (cls == 2) ? x : ((cls == 3) ? xl : xr);
    int cy = (cls == 0) ? y : yu;
    int cx = (cls == 0) ? xl : ((cls == 3) ? xr : x);
    float a = p[ay * IW + ax];
    float c = p[cy * IW + cx];
    float sup = (m0 > a && m0 > c) ? m0 : 0.f;
    g_edge[0][idx] = (sup > 150.0f) ? 1 : 0;
    g_low[0][idx]  = (sup >= 50.0f && sup < 150.0f) ? 1 : 0;
}

// ---------------------------------------------------------------------------
// Kernels 4/5: hysteresis iteration (zero-padded 3x3 any-neighbor).
// FINAL=true writes edges*255 as float directly to d_out.
// ---------------------------------------------------------------------------
template <int IN, bool FINAL>
__global__ void k_hyst(float* __restrict__ outE) {
    const int b = blockIdx.z;
    const int x = blockIdx.x * 32 + threadIdx.x;
    const int y = blockIdx.y * 8 + threadIdx.y;
    const int idx = b * NPIX + y * IW + x;
    const unsigned char* e = g_edge[IN] + b * NPIX;
    int nbr = 0;
#pragma unroll
    for (int dy = -1; dy <= 1; dy++) {
        int yy = y + dy;
        if (yy < 0 || yy >= IH) continue;
#pragma unroll
        for (int dx = -1; dx <= 1; dx++) {
            int xx = x + dx;
            if (xx < 0 || xx >= IW) continue;
            nbr |= e[yy * IW + xx];
        }
    }
    const unsigned char ec = e[y * IW + x];
    const unsigned char lc = g_low[IN][idx];
    const unsigned char conn = (nbr && lc) ? 1 : 0;
    const unsigned char enew = ec | conn;
    if (FINAL) {
        outE[idx] = enew ? 255.0f : 0.0f;
    } else {
        g_edge[IN ^ 1][idx] = enew;
        g_low[IN ^ 1][idx]  = (lc && !nbr) ? 1 : 0;
    }
}

extern "C" void kernel_launch(void* const* d_in, const int* in_sizes, int n_in,
                              void* d_out, int out_size) {
    const float* x   = (const float*)d_in[0];
    const float* gw  = (const float*)d_in[1];
    const float* sxw = (const float*)d_in[2];
    const float* syw = (const float*)d_in[3];
    float* out       = (float*)d_out;
    float* out_edges = out;
    float* out_mag   = out + NTOT;
    float* out_ang   = out + 2 * NTOT;

    dim3 blk(32, 8, 1);
    dim3 grd(IW / 32, IH / 8, IB);

    k_gauss<<<grd, blk>>>(x, gw);
    k_sobel<<<grd, blk>>>(sxw, syw, out_mag, out_ang);
    k_nms<<<grd, blk>>>(out_mag);
    k_hyst<0, false><<<grd, blk>>>(nullptr);
    k_hyst<1, true><<<grd, blk>>>(out_edges);
}

// round 2
// speedup vs baseline: 1.1807x; 1.1807x over previous
#include <cuda_runtime.h>

#define IW 1920
#define IH 1080
#define IB 8
#define NPIX (IW * IH)
#define NTOT (IB * NPIX)
#define WPR  (IW / 32)            // 60 packed words per row
#define NWORDS (NTOT / 32)        // 518400

// Scratch (no cudaMalloc allowed)
__device__ unsigned char g_dir[NTOT];
__device__ unsigned int  g_pe0[NWORDS], g_pl0[NWORDS];   // after NMS/threshold
__device__ unsigned int  g_pe1[NWORDS], g_pl1[NWORDS];   // after hysteresis iter 1

// ---------------------------------------------------------------------------
// Kernel 1: fused gaussian(5x5) + sobel + mag*255 + ang + direction class.
// Arithmetic is bit-identical to the round-1 two-kernel version.
// ---------------------------------------------------------------------------
__global__ void k_gausobel(const float* __restrict__ x, const float* __restrict__ gw,
                           const float* __restrict__ sxw, const float* __restrict__ syw,
                           float* __restrict__ magOut, float* __restrict__ angOut) {
    __shared__ float sin_[14][40];   // raw input tile, halo 3
    __shared__ float gsm[10][36];    // smoothed tile, halo 1 (zero outside image)
    __shared__ float wg[25], wx[9], wy[9];
    const int b  = blockIdx.z;
    const int bx = blockIdx.x * 32, by = blockIdx.y * 8;
    const int tx = threadIdx.x, ty = threadIdx.y;
    const int tid = ty * 32 + tx;
    if (tid < 25) wg[tid] = gw[tid];
    else if (tid >= 32 && tid < 41) wx[tid - 32] = sxw[tid - 32];
    else if (tid >= 64 && tid < 73) wy[tid - 64] = syw[tid - 64];
    const float* img = x + b * NPIX;
    for (int i = tid; i < 14 * 38; i += 256) {
        int r = i / 38, c = i % 38;
        int yy = by + r - 3, xx = bx + c - 3;
        float v = 0.f;
        if (yy >= 0 && yy < IH && xx >= 0 && xx < IW) v = img[yy * IW + xx];
        sin_[r][c] = v;
    }
    __syncthreads();
    for (int i = tid; i < 10 * 34; i += 256) {
        int r = i / 34, c = i % 34;
        int gy = by + r - 1, gx = bx + c - 1;
        float s = 0.f;
#pragma unroll
        for (int di = 0; di < 5; di++)
#pragma unroll
            for (int dj = 0; dj < 5; dj++)
                s = fmaf(wg[di * 5 + dj], sin_[r + di][c + dj], s);
        gsm[r][c] = (gy >= 0 && gy < IH && gx >= 0 && gx < IW) ? s * (1.0f / 255.0f) : 0.f;
    }
    __syncthreads();
    float gx_ = 0.f, gy_ = 0.f;
#pragma unroll
    for (int i = 0; i < 3; i++)
#pragma unroll
        for (int j = 0; j < 3; j++) {
            float v = gsm[ty + i][tx + j];
            gx_ = fmaf(wx[i * 3 + j], v, gx_);
            gy_ = fmaf(wy[i * 3 + j], v, gy_);
        }
    const int idx = b * NPIX + (by + ty) * IW + (bx + tx);
    float mag = sqrtf(gx_ * gx_ + gy_ * gy_ + 1e-6f);
    magOut[idx] = mag * 255.0f;
    float ang = atan2f(gy_, gx_);
    float t = ang + 3.14159274101257324f;          // float32(pi)
    t = fmodf(t, 6.28318548202514648f);            // float32(2*pi)
    float deg = t * 57.2957801818847656f;          // float32(180/pi)
    angOut[idx] = fmodf(deg, 180.0f);
    int q = (int)rintf(deg / 45.0f);               // round-half-even == jnp.round
    g_dir[idx] = (unsigned char)(q & 3);
}

// ---------------------------------------------------------------------------
// Kernel 2: NMS (wrap-around neighbors per jnp.roll) + double threshold
//           -> bit-packed edge/low maps via warp ballot.
// ---------------------------------------------------------------------------
__global__ void k_nms(const float* __restrict__ mag) {
    const int b = blockIdx.z;
    const int x = blockIdx.x * 32 + threadIdx.x;
    const int y = blockIdx.y * 8 + threadIdx.y;
    const float* p = mag + b * NPIX;
    const int idx = b * NPIX + y * IW + x;
    const float m0 = p[y * IW + x];
    const int xl = (x == 0) ? (IW - 1) : (x - 1);
    const int xr = (x == IW - 1) ? 0 : (x + 1);
    const int yu = (y == 0) ? (IH - 1) : (y - 1);
    const int yd = (y == IH - 1) ? 0 : (y + 1);
    const int cls = g_dir[idx];
    // cls0: (y,xr)/(y,xl)  cls1: (yd,xr)/(yu,x) [ref bug kept]
    // cls2: (yd,x)/(yu,x)  cls3: (yd,xl)/(yu,xr)
    int ay = (cls == 0) ? y : yd;
    int ax = (cls == 2) ? x : ((cls == 3) ? xl : xr);
    int cy = (cls == 0) ? y : yu;
    int cx = (cls == 0) ? xl : ((cls == 3) ? xr : x);
    float a = p[ay * IW + ax];
    float c = p[cy * IW + cx];
    float sup = (m0 > a && m0 > c) ? m0 : 0.f;
    unsigned we = __ballot_sync(0xffffffffu, sup > 150.0f);
    unsigned wl = __ballot_sync(0xffffffffu, sup >= 50.0f && sup < 150.0f);
    if (threadIdx.x == 0) {
        const int widx = (b * IH + y) * WPR + blockIdx.x;
        g_pe0[widx] = we;
        g_pl0[widx] = wl;
    }
}

// ---------------------------------------------------------------------------
// Bit helpers: OR of {left,center,right} horizontal neighbors of a word row,
// with cross-word carries. Zero-padded at image borders.
// ---------------------------------------------------------------------------
__device__ __forceinline__ unsigned hor3(unsigned L, unsigned M, unsigned R) {
    return M | (M << 1) | (M >> 1) | (L >> 31) | (R << 31);
}

// ---------------------------------------------------------------------------
// Kernel 3: hysteresis iteration 1, fully bit-packed.
// ---------------------------------------------------------------------------
__global__ void k_hyst1() {
    const int t = blockIdx.x * 256 + threadIdx.x;
    if (t >= NWORDS) return;
    const int w = t % WPR;
    const int rem = t / WPR;
    const int y = rem % IH;
    const int base = t - w;                 // word index of (b, y, 0)
    unsigned nbr = 0, e = 0;
#pragma unroll
    for (int dy = -1; dy <= 1; dy++) {
        const int yy = y + dy;
        if (yy < 0 || yy >= IH) continue;
        const int rb = base + dy * WPR;
        unsigned L = (w > 0)       ? g_pe0[rb + w - 1] : 0u;
        unsigned M =                 g_pe0[rb + w];
        unsigned R = (w < WPR - 1) ? g_pe0[rb + w + 1] : 0u;
        nbr |= hor3(L, M, R);
        if (dy == 0) e = M;
    }
    const unsigned l = g_pl0[t];
    const unsigned conn = nbr & l;
    g_pe1[t] = e | conn;
    g_pl1[t] = l & ~conn;
}

// ---------------------------------------------------------------------------
// Kernel 4: hysteresis iteration 2 + final edges*255 float store.
// Each warp owns one 32-pixel word; word math is warp-uniform (broadcast
// loads), each lane writes its own float.
// ---------------------------------------------------------------------------
__global__ void k_hyst2(float* __restrict__ outE) {
    const int b = blockIdx.z;
    const int w = blockIdx.x;
    const int y = blockIdx.y * 8 + threadIdx.y;
    const int lane = threadIdx.x;
    const int base = (b * IH + y) * WPR;
    unsigned nbr = 0, e = 0;
#pragma unroll
    for (int dy = -1; dy <= 1; dy++) {
        const int yy = y + dy;
        if (yy < 0 || yy >= IH) continue;
        const int rb = base + dy * WPR;
        unsigned L = (w > 0)       ? g_pe1[rb + w - 1] : 0u;
        unsigned M =                 g_pe1[rb + w];
        unsigned R = (w < WPR - 1) ? g_pe1[rb + w + 1] : 0u;
        nbr |= hor3(L, M, R);
        if (dy == 0) e = M;
    }
    const unsigned l = g_pl1[base + w];
    const unsigned enew = e | (nbr & l);
    const int pix = b * NPIX + y * IW + w * 32 + lane;
    outE[pix] = ((enew >> lane) & 1u) ? 255.0f : 0.0f;
}

extern "C" void kernel_launch(void* const* d_in, const int* in_sizes, int n_in,
                              void* d_out, int out_size) {
    const float* x   = (const float*)d_in[0];
    const float* gw  = (const float*)d_in[1];
    const float* sxw = (const float*)d_in[2];
    const float* syw = (const float*)d_in[3];
    float* out       = (float*)d_out;
    float* out_edges = out;
    float* out_mag   = out + NTOT;
    float* out_ang   = out + 2 * NTOT;

    dim3 blk(32, 8, 1);
    dim3 grd(IW / 32, IH / 8, IB);

    k_gausobel<<<grd, blk>>>(x, gw, sxw, syw, out_mag, out_ang);
    k_nms<<<grd, blk>>>(out_mag);
    k_hyst1<<<NWORDS / 256, 256>>>();
    k_hyst2<<<grd, blk>>>(out_edges);
}

// round 3
// speedup vs baseline: 1.2367x; 1.0475x over previous
#include <cuda_runtime.h>

#define IW 1920
#define IH 1080
#define IB 8
#define NPIX (IW * IH)
#define NTOT (IB * NPIX)
#define WPR  (IW / 32)            // 60 packed words per row
#define NWORDS (NTOT / 32)        // 518400
#define BORDER_WORDS_PER_IMG (60 + 60 + 1078 * 2)   // 2276

// Scratch (no cudaMalloc allowed)
__device__ unsigned char g_dir[NTOT];
__device__ unsigned int  g_pe0[NWORDS], g_pl0[NWORDS];   // after NMS/threshold
__device__ unsigned int  g_pe1[NWORDS], g_pl1[NWORDS];   // after hysteresis iter 1

// ---------------------------------------------------------------------------
// Kernel 1: fused gaussian(5x5) + sobel + mag*255 + ang + NMS + threshold.
// Tile pipeline: input 16x40 (halo 4) -> smoothed 12x36 (halo 2) ->
// mag 10x34 (halo 1) -> NMS 32x8. Arithmetic bit-identical to round 2.
// NMS is only valid for non-border pixels; border words are recomputed by
// k_border (jnp.roll wrap-around), overwriting whatever is stored here.
// ---------------------------------------------------------------------------
__global__ void k_fused(const float* __restrict__ x, const float* __restrict__ gw,
                        const float* __restrict__ sxw, const float* __restrict__ syw,
                        float* __restrict__ magOut, float* __restrict__ angOut) {
    __shared__ float sin_[16][42];   // raw input, halo 4 (16 rows x 40 cols used)
    __shared__ float gsm[12][38];    // smoothed/255, halo 2 (12 x 36 used)
    __shared__ float magS[10][36];   // mag*255, halo 1 (10 x 34 used)
    __shared__ float wg[25], wx[9], wy[9];
    const int b  = blockIdx.z;
    const int bx = blockIdx.x * 32, by = blockIdx.y * 8;
    const int tx = threadIdx.x, ty = threadIdx.y;
    const int tid = ty * 32 + tx;
    if (tid < 25) wg[tid] = gw[tid];
    else if (tid >= 32 && tid < 41) wx[tid - 32] = sxw[tid - 32];
    else if (tid >= 64 && tid < 73) wy[tid - 64] = syw[tid - 64];
    const float* img = x + b * NPIX;
    for (int i = tid; i < 16 * 40; i += 256) {
        int r = i / 40, c = i % 40;
        int yy = by + r - 4, xx = bx + c - 4;
        float v = 0.f;
        if (yy >= 0 && yy < IH && xx >= 0 && xx < IW) v = img[yy * IW + xx];
        sin_[r][c] = v;
    }
    __syncthreads();
    for (int i = tid; i < 12 * 36; i += 256) {
        int r = i / 36, c = i % 36;
        int yy = by + r - 2, xx = bx + c - 2;
        float s = 0.f;
#pragma unroll
        for (int di = 0; di < 5; di++)
#pragma unroll
            for (int dj = 0; dj < 5; dj++)
                s = fmaf(wg[di * 5 + dj], sin_[r + di][c + dj], s);
        gsm[r][c] = (yy >= 0 && yy < IH && xx >= 0 && xx < IW) ? s * (1.0f / 255.0f) : 0.f;
    }
    __syncthreads();
    for (int i = tid; i < 10 * 34; i += 256) {
        int r = i / 34, c = i % 34;
        float gxv = 0.f, gyv = 0.f;
#pragma unroll
        for (int di = 0; di < 3; di++)
#pragma unroll
            for (int dj = 0; dj < 3; dj++) {
                float v = gsm[r + di][c + dj];
                gxv = fmaf(wx[di * 3 + dj], v, gxv);
                gyv = fmaf(wy[di * 3 + dj], v, gyv);
            }
        magS[r][c] = sqrtf(gxv * gxv + gyv * gyv + 1e-6f) * 255.0f;
    }
    __syncthreads();
    // Own-pixel sobel (for angle) — identical arithmetic to the tile loop.
    float gx_ = 0.f, gy_ = 0.f;
#pragma unroll
    for (int di = 0; di < 3; di++)
#pragma unroll
        for (int dj = 0; dj < 3; dj++) {
            float v = gsm[ty + 1 + di][tx + 1 + dj];
            gx_ = fmaf(wx[di * 3 + dj], v, gx_);
            gy_ = fmaf(wy[di * 3 + dj], v, gy_);
        }
    const int Y = by + ty;
    const int idx = b * NPIX + Y * IW + (bx + tx);
    const float m255 = magS[ty + 1][tx + 1];
    magOut[idx] = m255;
    float ang = atan2f(gy_, gx_);
    float t = ang + 3.14159274101257324f;          // float32(pi)
    t = fmodf(t, 6.28318548202514648f);            // float32(2*pi)
    float deg = t * 57.2957801818847656f;          // float32(180/pi)
    angOut[idx] = fmodf(deg, 180.0f);
    int q = (int)rintf(deg / 45.0f);               // round-half-even == jnp.round
    const int cls = q & 3;
    // dir bytes only needed by k_border (border words)
    if (Y == 0 || Y == IH - 1 || blockIdx.x == 0 || blockIdx.x == WPR - 1)
        g_dir[idx] = (unsigned char)cls;
    // NMS from smem tile (valid for interior pixels; border overwritten later)
    const int r0 = ty + 1, c0 = tx + 1;
    // cls0: (y,xr)/(y,xl)  cls1: (yd,xr)/(yu,x) [ref bug kept]
    // cls2: (yd,x)/(yu,x)  cls3: (yd,xl)/(yu,xr)
    int ar = (cls == 0) ? r0 : r0 + 1;
    int ac = (cls == 2) ? c0 : ((cls == 3) ? c0 - 1 : c0 + 1);
    int cr = (cls == 0) ? r0 : r0 - 1;
    int cc = (cls == 0) ? c0 - 1 : ((cls == 3) ? c0 + 1 : c0);
    float a = magS[ar][ac];
    float c = magS[cr][cc];
    float sup = (m255 > a && m255 > c) ? m255 : 0.f;
    unsigned we = __ballot_sync(0xffffffffu, sup > 150.0f);
    unsigned wl = __ballot_sync(0xffffffffu, sup >= 50.0f && sup < 150.0f);
    if (tx == 0) {
        const int widx = (b * IH + Y) * WPR + blockIdx.x;
        g_pe0[widx] = we;
        g_pl0[widx] = wl;
    }
}

// ---------------------------------------------------------------------------
// Kernel 2: recompute NMS/threshold for border words (rows 0 & 1079, word
// cols 0 & 59) with jnp.roll wrap-around, reading the global mag written by
// k_fused. One warp per word.
// ---------------------------------------------------------------------------
__global__ void k_border(const float* __restrict__ mag) {
    const int W = blockIdx.x * 8 + threadIdx.y;          // warp id
    const int lane = threadIdx.x;
    const int b = W / BORDER_WORDS_PER_IMG;
    const int u = W % BORDER_WORDS_PER_IMG;
    int y, w;
    if (u < 60)       { y = 0;        w = u; }
    else if (u < 120) { y = IH - 1;   w = u - 60; }
    else { int v = u - 120; y = 1 + (v >> 1); w = (v & 1) ? (WPR - 1) : 0; }
    const int x = w * 32 + lane;
    const float* p = mag + b * NPIX;
    const int idx = b * NPIX + y * IW + x;
    const float m0 = p[y * IW + x];
    const int xl = (x == 0) ? (IW - 1) : (x - 1);
    const int xr = (x == IW - 1) ? 0 : (x + 1);
    const int yu = (y == 0) ? (IH - 1) : (y - 1);
    const int yd = (y == IH - 1) ? 0 : (y + 1);
    const int cls = g_dir[idx];
    int ay = (cls == 0) ? y : yd;
    int ax = (cls == 2) ? x : ((cls == 3) ? xl : xr);
    int cy = (cls == 0) ? y : yu;
    int cx = (cls == 0) ? xl : ((cls == 3) ? xr : x);
    float a = p[ay * IW + ax];
    float c = p[cy * IW + cx];
    float sup = (m0 > a && m0 > c) ? m0 : 0.f;
    unsigned we = __ballot_sync(0xffffffffu, sup > 150.0f);
    unsigned wl = __ballot_sync(0xffffffffu, sup >= 50.0f && sup < 150.0f);
    if (lane == 0) {
        const int widx = (b * IH + y) * WPR + w;
        g_pe0[widx] = we;
        g_pl0[widx] = wl;
    }
}

// ---------------------------------------------------------------------------
// Bit helper: OR of {left,center,right} horizontal neighbors of a word row.
// ---------------------------------------------------------------------------
__device__ __forceinline__ unsigned hor3(unsigned L, unsigned M, unsigned R) {
    return M | (M << 1) | (M >> 1) | (L >> 31) | (R << 31);
}

// ---------------------------------------------------------------------------
// Kernel 3: hysteresis iteration 1, fully bit-packed, word per thread.
// ---------------------------------------------------------------------------
__global__ void k_hyst1() {
    const int t = blockIdx.x * 256 + threadIdx.x;
    const int w = t % WPR;
    const int rem = t / WPR;
    const int y = rem % IH;
    const int base = t - w;
    unsigned nbr = 0, e = 0;
#pragma unroll
    for (int dy = -1; dy <= 1; dy++) {
        const int yy = y + dy;
        if (yy < 0 || yy >= IH) continue;
        const int rb = base + dy * WPR;
        unsigned L = (w > 0)       ? g_pe0[rb + w - 1] : 0u;
        unsigned M =                 g_pe0[rb + w];
        unsigned R = (w < WPR - 1) ? g_pe0[rb + w + 1] : 0u;
        nbr |= hor3(L, M, R);
        if (dy == 0) e = M;
    }
    const unsigned l = g_pl0[t];
    const unsigned conn = nbr & l;
    g_pe1[t] = e | conn;
    g_pl1[t] = l & ~conn;
}

// ---------------------------------------------------------------------------
// Kernel 4: hysteresis iteration 2 + final edges*255 float store.
// Word per thread; smem-staged, conflict-free, fully coalesced float output.
// ---------------------------------------------------------------------------
__global__ void k_hyst2(float* __restrict__ outE) {
    __shared__ float buf[256 * 33];
    const int t0 = blockIdx.x * 256;
    const int t = t0 + threadIdx.x;
    const int w = t % WPR;
    const int rem = t / WPR;
    const int y = rem % IH;
    const int base = t - w;
    unsigned nbr = 0, e = 0;
#pragma unroll
    for (int dy = -1; dy <= 1; dy++) {
        const int yy = y + dy;
        if (yy < 0 || yy >= IH) continue;
        const int rb = base + dy * WPR;
        unsigned L = (w > 0)       ? g_pe1[rb + w - 1] : 0u;
        unsigned M =                 g_pe1[rb + w];
        unsigned R = (w < WPR - 1) ? g_pe1[rb + w + 1] : 0u;
        nbr |= hor3(L, M, R);
        if (dy == 0) e = M;
    }
    const unsigned l = g_pl1[t];
    const unsigned enew = e | (nbr & l);
    // expand: thread writes its 32 bits at stride-33 row (bank = (lane+j)%32)
#pragma unroll
    for (int j = 0; j < 32; j++)
        buf[threadIdx.x * 33 + j] = ((enew >> j) & 1u) ? 255.0f : 0.0f;
    __syncthreads();
    // coalesced copy-out: consecutive tid -> consecutive pixels
    const int gbase = t0 * 32;
#pragma unroll
    for (int i = 0; i < 32; i++) {
        const int k = i * 256 + threadIdx.x;
        outE[gbase + k] = buf[(k >> 5) * 33 + (k & 31)];
    }
}

extern "C" void kernel_launch(void* const* d_in, const int* in_sizes, int n_in,
                              void* d_out, int out_size) {
    const float* x   = (const float*)d_in[0];
    const float* gw  = (const float*)d_in[1];
    const float* sxw = (const float*)d_in[2];
    const float* syw = (const float*)d_in[3];
    float* out       = (float*)d_out;
    float* out_edges = out;
    float* out_mag   = out + NTOT;
    float* out_ang   = out + 2 * NTOT;

    dim3 blk(32, 8, 1);
    dim3 grd(IW / 32, IH / 8, IB);

    k_fused<<<grd, blk>>>(x, gw, sxw, syw, out_mag, out_ang);
    k_border<<<(IB * BORDER_WORDS_PER_IMG) / 8, blk>>>(out_mag);
    k_hyst1<<<NWORDS / 256, 256>>>();
    k_hyst2<<<NWORDS / 256, 256>>>(out_edges);
}

// round 4
// speedup vs baseline: 1.6776x; 1.3565x over previous
#include <cuda_runtime.h>

#define IW 1920
#define IH 1080
#define IB 8
#define NPIX (IW * IH)
#define NTOT (IB * NPIX)
#define WPR  (IW / 32)            // 60 packed words per row
#define NWORDS (NTOT / 32)        // 518400
#define BORDER_WORDS_PER_IMG (60 + 60 + 1078 * 2)   // 2276

#define TH 24                     // output tile height (1080/24 = 45)

// Scratch (no cudaMalloc allowed)
__device__ unsigned char g_dir[NTOT];
__device__ unsigned int  g_pe0[NWORDS], g_pl0[NWORDS];   // after NMS/threshold
__device__ unsigned int  g_pe1[NWORDS], g_pl1[NWORDS];   // after hysteresis iter 1

// ---------------------------------------------------------------------------
// Kernel 1: fused gaussian(5x5) + sobel + mag*255 + ang + NMS + threshold.
// 32x24-output tile per 256-thread block; 3 output px per thread.
// Pipeline: input 32x40 (halo 4) -> smoothed 28x36 (halo 2) ->
// mag 26x34 (halo 1) -> NMS 32x24. Arithmetic bit-identical to round 3
// (fmodf replaced by exact conditional subtracts).
// Border words (jnp.roll wrap) are recomputed by k_border afterwards.
// ---------------------------------------------------------------------------
__global__ void k_fused(const float* __restrict__ x, const float* __restrict__ gw,
                        const float* __restrict__ sxw, const float* __restrict__ syw,
                        float* __restrict__ magOut, float* __restrict__ angOut) {
    __shared__ float sin_[32][41];   // raw input, rows by-4..by+27, cols bx-4..bx+35
    __shared__ float gsm[28][37];    // smoothed/255, rows by-2..by+25, cols bx-2..bx+33
    __shared__ float magS[26][35];   // mag*255, rows by-1..by+24, cols bx-1..bx+33
    __shared__ float wg[25], wx[9], wy[9];
    const int b  = blockIdx.z;
    const int bx = blockIdx.x * 32, by = blockIdx.y * TH;
    const int tx = threadIdx.x, ty = threadIdx.y;
    const int tid = ty * 32 + tx;
    if (tid < 25) wg[tid] = gw[tid];
    else if (tid >= 32 && tid < 41) wx[tid - 32] = sxw[tid - 32];
    else if (tid >= 64 && tid < 73) wy[tid - 64] = syw[tid - 64];
    const float* img = x + b * NPIX;
    // ---- stage 0: raw input tile (zero padded) ----
    for (int i = tid; i < 32 * 40; i += 256) {
        int r = i / 40, c = i % 40;
        int yy = by + r - 4, xx = bx + c - 4;
        float v = 0.f;
        if (yy >= 0 && yy < IH && xx >= 0 && xx < IW) v = img[yy * IW + xx];
        sin_[r][c] = v;
    }
    __syncthreads();
    // ---- stage 1: gaussian -> gsm ----
    for (int i = tid; i < 28 * 36; i += 256) {
        int r = i / 36, c = i % 36;
        int yy = by + r - 2, xx = bx + c - 2;
        float s = 0.f;
#pragma unroll
        for (int di = 0; di < 5; di++)
#pragma unroll
            for (int dj = 0; dj < 5; dj++)
                s = fmaf(wg[di * 5 + dj], sin_[r + di][c + dj], s);
        gsm[r][c] = (yy >= 0 && yy < IH && xx >= 0 && xx < IW) ? s * (1.0f / 255.0f) : 0.f;
    }
    __syncthreads();
    // ---- stage 2: sobel magnitude -> magS ----
    for (int i = tid; i < 26 * 34; i += 256) {
        int r = i / 34, c = i % 34;
        float gxv = 0.f, gyv = 0.f;
#pragma unroll
        for (int di = 0; di < 3; di++)
#pragma unroll
            for (int dj = 0; dj < 3; dj++) {
                float v = gsm[r + di][c + dj];
                gxv = fmaf(wx[di * 3 + dj], v, gxv);
                gyv = fmaf(wy[di * 3 + dj], v, gyv);
            }
        magS[r][c] = sqrtf(gxv * gxv + gyv * gyv + 1e-6f) * 255.0f;
    }
    __syncthreads();
    // ---- stage 3: per-pixel angle + outputs + NMS (3 rows per thread) ----
    const bool colBorder = (blockIdx.x == 0) | (blockIdx.x == WPR - 1);
#pragma unroll
    for (int s = 0; s < 3; s++) {
        const int o = ty + 8 * s;            // output row within tile (warp-uniform)
        const int Y = by + o;
        const int idx = b * NPIX + Y * IW + (bx + tx);
        // own-pixel sobel for angle (same arithmetic as stage-2 loop)
        float gx_ = 0.f, gy_ = 0.f;
#pragma unroll
        for (int di = 0; di < 3; di++)
#pragma unroll
            for (int dj = 0; dj < 3; dj++) {
                float v = gsm[o + 1 + di][tx + 1 + dj];
                gx_ = fmaf(wx[di * 3 + dj], v, gx_);
                gy_ = fmaf(wy[di * 3 + dj], v, gy_);
            }
        const float m255 = magS[o + 1][tx + 1];
        magOut[idx] = m255;
        float ang = atan2f(gy_, gx_);
        float t = ang + 3.14159274101257324f;            // float32(pi)
        if (t >= 6.28318548202514648f) t -= 6.28318548202514648f;   // == fmodf(t, 2pi)
        float deg = t * 57.2957801818847656f;            // float32(180/pi)
        float am = deg;
        if (am >= 180.0f) am -= 180.0f;                  // == fmodf(deg, 180)
        if (am >= 180.0f) am -= 180.0f;
        angOut[idx] = am;
        int q = (int)rintf(deg / 45.0f);                 // round-half-even == jnp.round
        const int cls = q & 3;
        if (Y == 0 || Y == IH - 1 || colBorder)
            g_dir[idx] = (unsigned char)cls;
        // NMS from smem (interior-valid; border words overwritten by k_border)
        const int r0 = o + 1, c0 = tx + 1;
        // cls0: (y,xr)/(y,xl)  cls1: (yd,xr)/(yu,x) [ref bug kept]
        // cls2: (yd,x)/(yu,x)  cls3: (yd,xl)/(yu,xr)
        int ar = (cls == 0) ? r0 : r0 + 1;
        int ac = (cls == 2) ? c0 : ((cls == 3) ? c0 - 1 : c0 + 1);
        int cr = (cls == 0) ? r0 : r0 - 1;
        int cc = (cls == 0) ? c0 - 1 : ((cls == 3) ? c0 + 1 : c0);
        float a = magS[ar][ac];
        float c = magS[cr][cc];
        float sup = (m255 > a && m255 > c) ? m255 : 0.f;
        unsigned we = __ballot_sync(0xffffffffu, sup > 150.0f);
        unsigned wl = __ballot_sync(0xffffffffu, sup >= 50.0f && sup < 150.0f);
        if (tx == 0) {
            const int widx = (b * IH + Y) * WPR + blockIdx.x;
            g_pe0[widx] = we;
            g_pl0[widx] = wl;
        }
    }
}

// ---------------------------------------------------------------------------
// Kernel 2: recompute NMS/threshold for border words (rows 0 & 1079, word
// cols 0 & 59) with jnp.roll wrap-around. One warp per word.
// ---------------------------------------------------------------------------
__global__ void k_border(const float* __restrict__ mag) {
    const int W = blockIdx.x * 8 + threadIdx.y;          // warp id
    const int lane = threadIdx.x;
    const int b = W / BORDER_WORDS_PER_IMG;
    const int u = W % BORDER_WORDS_PER_IMG;
    int y, w;
    if (u < 60)       { y = 0;        w = u; }
    else if (u < 120) { y = IH - 1;   w = u - 60; }
    else { int v = u - 120; y = 1 + (v >> 1); w = (v & 1) ? (WPR - 1) : 0; }
    const int x = w * 32 + lane;
    const float* p = mag + b * NPIX;
    const int idx = b * NPIX + y * IW + x;
    const float m0 = p[y * IW + x];
    const int xl = (x == 0) ? (IW - 1) : (x - 1);
    const int xr = (x == IW - 1) ? 0 : (x + 1);
    const int yu = (y == 0) ? (IH - 1) : (y - 1);
    const int yd = (y == IH - 1) ? 0 : (y + 1);
    const int cls = g_dir[idx];
    int ay = (cls == 0) ? y : yd;
    int ax = (cls == 2) ? x : ((cls == 3) ? xl : xr);
    int cy = (cls == 0) ? y : yu;
    int cx = (cls == 0) ? xl : ((cls == 3) ? xr : x);
    float a = p[ay * IW + ax];
    float c = p[cy * IW + cx];
    float sup = (m0 > a && m0 > c) ? m0 : 0.f;
    unsigned we = __ballot_sync(0xffffffffu, sup > 150.0f);
    unsigned wl = __ballot_sync(0xffffffffu, sup >= 50.0f && sup < 150.0f);
    if (lane == 0) {
        const int widx = (b * IH + y) * WPR + w;
        g_pe0[widx] = we;
        g_pl0[widx] = wl;
    }
}

// ---------------------------------------------------------------------------
// Bit helper: OR of {left,center,right} horizontal neighbors of a word row.
// ---------------------------------------------------------------------------
__device__ __forceinline__ unsigned hor3(unsigned L, unsigned M, unsigned R) {
    return M | (M << 1) | (M >> 1) | (L >> 31) | (R << 31);
}

// ---------------------------------------------------------------------------
// Kernel 3: hysteresis iteration 1, fully bit-packed, word per thread.
// ---------------------------------------------------------------------------
__global__ void k_hyst1() {
    const int t = blockIdx.x * 256 + threadIdx.x;
    const int w = t % WPR;
    const int rem = t / WPR;
    const int y = rem % IH;
    const int base = t - w;
    unsigned nbr = 0, e = 0;
#pragma unroll
    for (int dy = -1; dy <= 1; dy++) {
        const int yy = y + dy;
        if (yy < 0 || yy >= IH) continue;
        const int rb = base + dy * WPR;
        unsigned L = (w > 0)       ? g_pe0[rb + w - 1] : 0u;
        unsigned M =                 g_pe0[rb + w];
        unsigned R = (w < WPR - 1) ? g_pe0[rb + w + 1] : 0u;
        nbr |= hor3(L, M, R);
        if (dy == 0) e = M;
    }
    const unsigned l = g_pl0[t];
    const unsigned conn = nbr & l;
    g_pe1[t] = e | conn;
    g_pl1[t] = l & ~conn;
}

// ---------------------------------------------------------------------------
// Kernel 4: hysteresis iteration 2 + final edges*255 float store.
// Word per thread; smem-staged, conflict-free, fully coalesced float output.
// ---------------------------------------------------------------------------
__global__ void k_hyst2(float* __restrict__ outE) {
    __shared__ float buf[256 * 33];
    const int t0 = blockIdx.x * 256;
    const int t = t0 + threadIdx.x;
    const int w = t % WPR;
    const int rem = t / WPR;
    const int y = rem % IH;
    const int base = t - w;
    unsigned nbr = 0, e = 0;
#pragma unroll
    for (int dy = -1; dy <= 1; dy++) {
        const int yy = y + dy;
        if (yy < 0 || yy >= IH) continue;
        const int rb = base + dy * WPR;
        unsigned L = (w > 0)       ? g_pe1[rb + w - 1] : 0u;
        unsigned M =                 g_pe1[rb + w];
        unsigned R = (w < WPR - 1) ? g_pe1[rb + w + 1] : 0u;
        nbr |= hor3(L, M, R);
        if (dy == 0) e = M;
    }
    const unsigned l = g_pl1[t];
    const unsigned enew = e | (nbr & l);
#pragma unroll
    for (int j = 0; j < 32; j++)
        buf[threadIdx.x * 33 + j] = ((enew >> j) & 1u) ? 255.0f : 0.0f;
    __syncthreads();
    const int gbase = t0 * 32;
#pragma unroll
    for (int i = 0; i < 32; i++) {
        const int k = i * 256 + threadIdx.x;
        outE[gbase + k] = buf[(k >> 5) * 33 + (k & 31)];
    }
}

extern "C" void kernel_launch(void* const* d_in, const int* in_sizes, int n_in,
                              void* d_out, int out_size) {
    const float* x   = (const float*)d_in[0];
    const float* gw  = (const float*)d_in[1];
    const float* sxw = (const float*)d_in[2];
    const float* syw = (const float*)d_in[3];
    float* out       = (float*)d_out;
    float* out_edges = out;
    float* out_mag   = out + NTOT;
    float* out_ang   = out + 2 * NTOT;

    dim3 blk(32, 8, 1);
    dim3 grd(IW / 32, IH / TH, IB);

    k_fused<<<grd, blk>>>(x, gw, sxw, syw, out_mag, out_ang);
    k_border<<<(IB * BORDER_WORDS_PER_IMG) / 8, blk>>>(out_mag);
    k_hyst1<<<NWORDS / 256, 256>>>();
    k_hyst2<<<NWORDS / 256, 256>>>(out_edges);
}